// round 1
// baseline (speedup 1.0000x reference)
#include <cuda_runtime.h>
#include <cuda_bf16.h>

// Problem constants
#define NN 200000
#define EE 600000
#define GG 8192
#define HH 128
#define DIN 30

// ---------------- scratch (device globals; no allocations allowed) ----------
__device__ float g_act[(size_t)NN * HH];   // layer input activations (layer1: padded x, stride 32)
__device__ float g_h[(size_t)NN * HH];     // h = act @ W
__device__ float g_agg[(size_t)NN * HH];   // aggregation buffer
__device__ float g_dinv[NN];               // deg -> rsqrt(deg)
__device__ float g_invcnt[GG];             // counts -> 1/max(count,1)

// ---------------- init: zero output, deg=1 (self loop), counts=0 ------------
__global__ void init_kernel(float* __restrict__ out) {
    int idx = blockIdx.x * blockDim.x + threadIdx.x;
    if (idx < GG * HH) out[idx] = 0.0f;
    if (idx < NN) g_dinv[idx] = 1.0f;
    if (idx < GG) g_invcnt[idx] = 0.0f;
}

// ---------------- degree + batch counts -------------------------------------
__global__ void count_kernel(const int* __restrict__ dst, const int* __restrict__ batch_idx) {
    int idx = blockIdx.x * blockDim.x + threadIdx.x;
    if (idx < EE) atomicAdd(&g_dinv[dst[idx]], 1.0f);
    if (idx < NN) atomicAdd(&g_invcnt[batch_idx[idx]], 1.0f);
}

__global__ void finalize_kernel() {
    int idx = blockIdx.x * blockDim.x + threadIdx.x;
    if (idx < NN) g_dinv[idx] = rsqrtf(g_dinv[idx]);
    if (idx < GG) g_invcnt[idx] = 1.0f / fmaxf(g_invcnt[idx], 1.0f);
}

// ---------------- pad x [N,30] -> g_act [N,32] ------------------------------
__global__ void pad_x_kernel(const float* __restrict__ x) {
    int idx = blockIdx.x * blockDim.x + threadIdx.x;   // over N*32
    if (idx >= NN * 32) return;
    int n = idx >> 5;
    int k = idx & 31;
    g_act[idx] = (k < DIN) ? x[n * DIN + k] : 0.0f;
}

// ---------------- GEMM: h = act @ W ; agg = h * dinv^2 ----------------------
// 256 threads/block, tile = 64 nodes x 128 cols, 8x4 accumulators per thread.
template <int KPAD, int KW>
__global__ void __launch_bounds__(256) gemm_kernel(const float* __restrict__ act,
                                                   const float* __restrict__ W,
                                                   float* __restrict__ h,
                                                   float* __restrict__ agg) {
    constexpr int KB = 32;
    __shared__ float Ws[KB][HH];
    __shared__ float Xs[64][KB];

    const int tid  = threadIdx.x;
    const int col  = (tid & 31) * 4;      // 4 contiguous cols per lane (covers 128)
    const int rb   = tid >> 5;            // row base 0..7
    const int node0 = blockIdx.x * 64;

    float acc[8][4];
#pragma unroll
    for (int i = 0; i < 8; i++) { acc[i][0] = acc[i][1] = acc[i][2] = acc[i][3] = 0.f; }

    for (int k0 = 0; k0 < KPAD; k0 += KB) {
        // stage W chunk [KB x 128] (zero-pad rows >= KW)
#pragma unroll
        for (int i = 0; i < 4; i++) {
            int j  = tid + 256 * i;         // float4 index 0..1023
            int kr = j >> 5;                // chunk row
            int cc = (j & 31) * 4;
            int kg = k0 + kr;
            float4 wv = make_float4(0.f, 0.f, 0.f, 0.f);
            if (kg < KW) wv = *(const float4*)&W[kg * HH + cc];
            *(float4*)&Ws[kr][cc] = wv;
        }
        // stage X chunk [64 x KB]
#pragma unroll
        for (int i = 0; i < 2; i++) {
            int j  = tid + 256 * i;         // float4 index 0..511
            int r  = j >> 3;
            int c4 = (j & 7) * 4;
            float4 xv = *(const float4*)&act[(size_t)(node0 + r) * KPAD + k0 + c4];
            *(float4*)&Xs[r][c4] = xv;
        }
        __syncthreads();
#pragma unroll
        for (int kk = 0; kk < KB; kk++) {
            float4 wv = *(const float4*)&Ws[kk][col];
#pragma unroll
            for (int i = 0; i < 8; i++) {
                float xv = Xs[rb + 8 * i][kk];
                acc[i][0] += xv * wv.x;
                acc[i][1] += xv * wv.y;
                acc[i][2] += xv * wv.z;
                acc[i][3] += xv * wv.w;
            }
        }
        __syncthreads();
    }
#pragma unroll
    for (int i = 0; i < 8; i++) {
        int n = node0 + rb + 8 * i;
        float dv = g_dinv[n];
        float d2 = dv * dv;
        float4 hv = make_float4(acc[i][0], acc[i][1], acc[i][2], acc[i][3]);
        *(float4*)&h[(size_t)n * HH + col] = hv;
        float4 av = make_float4(hv.x * d2, hv.y * d2, hv.z * d2, hv.w * d2);
        *(float4*)&agg[(size_t)n * HH + col] = av;
    }
}

// ---------------- edge scatter: agg[dst] += h[src] * dinv[s]*dinv[d] --------
// one warp per edge; each lane handles 4 floats; vector L2 reduction.
__global__ void __launch_bounds__(256) scatter_kernel(const int* __restrict__ src,
                                                      const int* __restrict__ dst) {
    int e = blockIdx.x * 8 + (threadIdx.x >> 5);
    if (e >= EE) return;
    int lane = threadIdx.x & 31;
    int s = __ldg(&src[e]);
    int d = __ldg(&dst[e]);
    float w = g_dinv[s] * g_dinv[d];
    float4 v = *(const float4*)&g_h[(size_t)s * HH + lane * 4];
    float4 m = make_float4(v.x * w, v.y * w, v.z * w, v.w * w);
    float* p = &g_agg[(size_t)d * HH + lane * 4];
    asm volatile("red.global.add.v4.f32 [%0], {%1, %2, %3, %4};"
                 :: "l"(p), "f"(m.x), "f"(m.y), "f"(m.z), "f"(m.w)
                 : "memory");
}

// ---------------- epilogue: act = relu(agg + b) ------------------------------
__global__ void epilogue_relu_kernel(const float* __restrict__ bias) {
    int idx = blockIdx.x * blockDim.x + threadIdx.x;   // over N*32 (float4 units)
    if (idx >= NN * 32) return;
    int n  = idx >> 5;
    int c4 = (idx & 31) * 4;
    float4 a = *(const float4*)&g_agg[(size_t)n * HH + c4];
    float4 b = *(const float4*)&bias[c4];
    float4 r = make_float4(fmaxf(a.x + b.x, 0.f), fmaxf(a.y + b.y, 0.f),
                           fmaxf(a.z + b.z, 0.f), fmaxf(a.w + b.w, 0.f));
    *(float4*)&g_act[(size_t)n * HH + c4] = r;
}

// ---------------- final: relu + bias + mean-pool into out -------------------
__global__ void epilogue_pool_kernel(const float* __restrict__ bias,
                                     const int* __restrict__ batch_idx,
                                     float* __restrict__ out) {
    int idx = blockIdx.x * blockDim.x + threadIdx.x;   // over N*32
    if (idx >= NN * 32) return;
    int n  = idx >> 5;
    int c4 = (idx & 31) * 4;
    int g  = __ldg(&batch_idx[n]);
    float w = g_invcnt[g];
    float4 a = *(const float4*)&g_agg[(size_t)n * HH + c4];
    float4 b = *(const float4*)&bias[c4];
    float4 r = make_float4(fmaxf(a.x + b.x, 0.f) * w, fmaxf(a.y + b.y, 0.f) * w,
                           fmaxf(a.z + b.z, 0.f) * w, fmaxf(a.w + b.w, 0.f) * w);
    float* p = &out[(size_t)g * HH + c4];
    asm volatile("red.global.add.v4.f32 [%0], {%1, %2, %3, %4};"
                 :: "l"(p), "f"(r.x), "f"(r.y), "f"(r.z), "f"(r.w)
                 : "memory");
}

// ---------------- launch ------------------------------------------------------
extern "C" void kernel_launch(void* const* d_in, const int* in_sizes, int n_in,
                              void* d_out, int out_size) {
    const float* x         = (const float*)d_in[0];
    const int*   edge      = (const int*)d_in[1];     // [2, E]
    const int*   batch_idx = (const int*)d_in[2];
    const float* W1        = (const float*)d_in[3];
    const float* b1        = (const float*)d_in[4];
    const float* W2        = (const float*)d_in[5];
    const float* b2        = (const float*)d_in[6];
    const float* W3        = (const float*)d_in[7];
    const float* b3        = (const float*)d_in[8];
    float* out = (float*)d_out;

    const int* src = edge;
    const int* dst = edge + EE;

    float *h, *agg, *act;
    cudaGetSymbolAddress((void**)&h,   g_h);
    cudaGetSymbolAddress((void**)&agg, g_agg);
    cudaGetSymbolAddress((void**)&act, g_act);

    const int T = 256;
    // init (covers G*H = 1,048,576 which also covers N and G)
    init_kernel<<<(GG * HH + T - 1) / T, T>>>(out);
    // degrees + batch counts (covers E > N)
    count_kernel<<<(EE + T - 1) / T, T>>>(dst, batch_idx);
    finalize_kernel<<<(NN + T - 1) / T, T>>>();
    // pad x to stride 32
    pad_x_kernel<<<(NN * 32 + T - 1) / T, T>>>(x);

    const int gemm_grid    = NN / 64;            // 3125
    const int scatter_grid = (EE + 7) / 8;       // 75000
    const int vec_grid     = (NN * 32 + T - 1) / T;

    // ---- layer 1 (K=30, padded to 32)
    gemm_kernel<32, DIN><<<gemm_grid, T>>>(act, W1, h, agg);
    scatter_kernel<<<scatter_grid, T>>>(src, dst);
    epilogue_relu_kernel<<<vec_grid, T>>>(b1);

    // ---- layer 2
    gemm_kernel<HH, HH><<<gemm_grid, T>>>(act, W2, h, agg);
    scatter_kernel<<<scatter_grid, T>>>(src, dst);
    epilogue_relu_kernel<<<vec_grid, T>>>(b2);

    // ---- layer 3 (fused relu+bias+mean-pool)
    gemm_kernel<HH, HH><<<gemm_grid, T>>>(act, W3, h, agg);
    scatter_kernel<<<scatter_grid, T>>>(src, dst);
    epilogue_pool_kernel<<<vec_grid, T>>>(b3, batch_idx, out);
}